// round 1
// baseline (speedup 1.0000x reference)
#include <cuda_runtime.h>
#include <math.h>

#define NN   100000
#define EE   1600000
#define FIN  256
#define FOUT 128

// Scratch (static __device__ — no allocations allowed)
__device__ float g_y[(size_t)NN * FOUT];     // y = (feature @ W) * dinv[row]
__device__ float g_s[(size_t)NN * FOUT];     // s = y (self loop) + scatter of y[row]
__device__ float g_deg[NN];
__device__ float g_dinv[NN];
__device__ float g_hsum[FOUT];

// ---------------------------------------------------------------------------
// 1. init: deg = 1 (self loop), hsum = 0
__global__ void k_init(int n) {
    int i = blockIdx.x * blockDim.x + threadIdx.x;
    if (i < n)    g_deg[i]  = 1.0f;
    if (i < FOUT) g_hsum[i] = 0.0f;
}

// 2. in-degree over edges (dest = col)
__global__ void k_deg(const int* __restrict__ col, int e) {
    int i = blockIdx.x * blockDim.x + threadIdx.x;
    if (i < e) atomicAdd(&g_deg[col[i]], 1.0f);
}

// 3. dinv = rsqrt(deg)  (deg >= 1 always, self loop)
__global__ void k_dinv(int n) {
    int i = blockIdx.x * blockDim.x + threadIdx.x;
    if (i < n) g_dinv[i] = rsqrtf(g_deg[i]);
}

// ---------------------------------------------------------------------------
// 4. SGEMM: y = (A @ W) * dinv[row];  s initialized to y (self-loop term).
//    Tile 128x128, K-step 8, 256 threads, 8x8 micro-tile per thread.
__global__ void __launch_bounds__(256, 2)
k_gemm(const float* __restrict__ A, const float* __restrict__ W, int N) {
    __shared__ float As[8][132];   // [k][m], padded
    __shared__ float Bs[8][128];   // [k][n]

    const int tx = threadIdx.x;
    const int block_row = blockIdx.x * 128;
    const int tid_r = tx >> 4;          // 0..15
    const int tid_c = tx & 15;          // 0..15

    float acc[8][8];
#pragma unroll
    for (int i = 0; i < 8; i++)
#pragma unroll
        for (int j = 0; j < 8; j++) acc[i][j] = 0.0f;

    const int lrow = tx >> 1;           // 0..127 (A-load row)
    const int half = tx & 1;            // which 4-float chunk of the 8-wide K slab
    const int gr_load = block_row + lrow;
    const int bk = tx >> 5;             // 0..7  (B-load k row)
    const int bc = tx & 31;             // 0..31 (B-load float4 col)

    for (int k0 = 0; k0 < FIN; k0 += 8) {
        float4 av = make_float4(0.f, 0.f, 0.f, 0.f);
        if (gr_load < N)
            av = *(const float4*)(A + (size_t)gr_load * FIN + k0 + half * 4);
        As[half * 4 + 0][lrow] = av.x;
        As[half * 4 + 1][lrow] = av.y;
        As[half * 4 + 2][lrow] = av.z;
        As[half * 4 + 3][lrow] = av.w;

        float4 bv = *(const float4*)(W + (size_t)(k0 + bk) * FOUT + bc * 4);
        *(float4*)&Bs[bk][bc * 4] = bv;

        __syncthreads();
#pragma unroll
        for (int kk = 0; kk < 8; kk++) {
            float a[8], b[8];
#pragma unroll
            for (int i = 0; i < 8; i++) a[i] = As[kk][tid_r * 8 + i];
#pragma unroll
            for (int j = 0; j < 8; j++) b[j] = Bs[kk][tid_c * 8 + j];
#pragma unroll
            for (int i = 0; i < 8; i++)
#pragma unroll
                for (int j = 0; j < 8; j++) acc[i][j] = fmaf(a[i], b[j], acc[i][j]);
        }
        __syncthreads();
    }

#pragma unroll
    for (int i = 0; i < 8; i++) {
        int gr = block_row + tid_r * 8 + i;
        if (gr >= N) continue;
        float dv = g_dinv[gr];
#pragma unroll
        for (int j = 0; j < 8; j += 4) {
            float4 v;
            v.x = acc[i][j + 0] * dv;
            v.y = acc[i][j + 1] * dv;
            v.z = acc[i][j + 2] * dv;
            v.w = acc[i][j + 3] * dv;
            size_t idx = (size_t)gr * FOUT + tid_c * 8 + j;
            *(float4*)(g_y + idx) = v;
            *(float4*)(g_s + idx) = v;   // self-loop init
        }
    }
}

// ---------------------------------------------------------------------------
// 5. Edge scatter: one warp per edge. s[col] += y[row] (128 floats = 32 float4
//    lanes), vectorized reduction to L2.
__global__ void k_scatter(const int* __restrict__ row, const int* __restrict__ col, int e) {
    int w = (blockIdx.x * blockDim.x + threadIdx.x) >> 5;
    int lane = threadIdx.x & 31;
    if (w >= e) return;
    int r = __ldg(&row[w]);
    int c = __ldg(&col[w]);
    float4 v = ((const float4*)(g_y + (size_t)r * FOUT))[lane];
    float* dst = g_s + (size_t)c * FOUT + lane * 4;
    asm volatile("red.global.add.v4.f32 [%0], {%1, %2, %3, %4};"
                 :: "l"(dst), "f"(v.x), "f"(v.y), "f"(v.z), "f"(v.w)
                 : "memory");
}

// ---------------------------------------------------------------------------
// 6. Epilogue: x_out = relu(dinv*s + b), write d_out; accumulate column sums.
//    One warp per node (8 nodes / 256-thread block), lane covers 4 features.
__global__ void k_out(const float* __restrict__ b, float* __restrict__ out, int N) {
    __shared__ float hpart[FOUT];
    int tx = threadIdx.x;
    if (tx < FOUT) hpart[tx] = 0.0f;
    __syncthreads();

    int lane = tx & 31;
    int warp = tx >> 5;
    int node = blockIdx.x * 8 + warp;
    float4 v = make_float4(0.f, 0.f, 0.f, 0.f);
    if (node < N) {
        float dv = g_dinv[node];
        float4 sv = ((const float4*)(g_s + (size_t)node * FOUT))[lane];
        float4 bv = ((const float4*)b)[lane];
        v.x = fmaxf(fmaf(sv.x, dv, bv.x), 0.0f);
        v.y = fmaxf(fmaf(sv.y, dv, bv.y), 0.0f);
        v.z = fmaxf(fmaf(sv.z, dv, bv.z), 0.0f);
        v.w = fmaxf(fmaf(sv.w, dv, bv.w), 0.0f);
        ((float4*)(out + (size_t)node * FOUT))[lane] = v;
    }
    atomicAdd(&hpart[lane * 4 + 0], v.x);
    atomicAdd(&hpart[lane * 4 + 1], v.y);
    atomicAdd(&hpart[lane * 4 + 2], v.z);
    atomicAdd(&hpart[lane * 4 + 3], v.w);
    __syncthreads();
    if (tx < FOUT) atomicAdd(&g_hsum[tx], hpart[tx]);
}

// 7. h = sigmoid(mean)
__global__ void k_h(float* __restrict__ hout, float ninv) {
    int j = threadIdx.x;
    float m = g_hsum[j] * ninv;
    hout[j] = 1.0f / (1.0f + expf(-m));
}

// ---------------------------------------------------------------------------
extern "C" void kernel_launch(void* const* d_in, const int* in_sizes, int n_in,
                              void* d_out, int out_size) {
    const float* feat = (const float*)d_in[0];
    const int*   ei   = (const int*)d_in[1];
    const float* W    = (const float*)d_in[2];
    const float* b    = (const float*)d_in[3];
    float* out = (float*)d_out;

    int N = in_sizes[0] / FIN;
    int E = in_sizes[1] / 2;
    const int* rowp = ei;
    const int* colp = ei + E;

    k_init<<<(N + 255) / 256, 256>>>(N);
    k_deg<<<(E + 255) / 256, 256>>>(colp, E);
    k_dinv<<<(N + 255) / 256, 256>>>(N);
    k_gemm<<<(N + 127) / 128, 256>>>(feat, W, N);
    k_scatter<<<(E + 7) / 8, 256>>>(rowp, colp, E);
    k_out<<<(N + 7) / 8, 256>>>(b, out, N);
    k_h<<<1, FOUT>>>(out + (size_t)N * FOUT, 1.0f / (float)N);
}

// round 2
// speedup vs baseline: 1.4906x; 1.4906x over previous
#include <cuda_runtime.h>
#include <math.h>

#define NN   100000
#define EE   1600000
#define FIN  256
#define FOUT 128
#define SCAN_BLK 1024
#define NBLK ((NN + SCAN_BLK - 1) / SCAN_BLK)   // 98

// Scratch (static __device__)
__device__ float g_y[(size_t)NN * FOUT];   // y = (feature @ W) * dinv[row]
__device__ int   g_degi[NN];               // edge in-degree (no self loop)
__device__ float g_dinv[NN];               // rsqrt(deg+1)
__device__ int   g_start[NN];              // exclusive scan of g_degi
__device__ int   g_cursor[NN];             // running cursors for sort
__device__ int   g_srow[EE];               // row indices sorted by col
__device__ int   g_bsum[NBLK];             // scan block partials
__device__ float g_hsum[FOUT];

// ---------------------------------------------------------------------------
// 1. zero degree histogram
__global__ void k_zero(int n) {
    int i = blockIdx.x * blockDim.x + threadIdx.x;
    if (i < n) g_degi[i] = 0;
}

// 2. in-degree histogram over edges (dest = col)
__global__ void k_deg(const int* __restrict__ col, int e) {
    int i = blockIdx.x * blockDim.x + threadIdx.x;
    if (i < e) atomicAdd(&g_degi[col[i]], 1);
}

// 3. dinv = rsqrt(deg + 1)   (+1 = self loop)
__global__ void k_dinv(int n) {
    int i = blockIdx.x * blockDim.x + threadIdx.x;
    if (i < n) g_dinv[i] = rsqrtf((float)(g_degi[i] + 1));
}

// 4a. block-level exclusive scan of g_degi
__global__ void k_scan1() {
    __shared__ int sd[SCAN_BLK];
    int tx = threadIdx.x;
    int i = blockIdx.x * SCAN_BLK + tx;
    int v = (i < NN) ? g_degi[i] : 0;
    sd[tx] = v;
    __syncthreads();
#pragma unroll
    for (int off = 1; off < SCAN_BLK; off <<= 1) {
        int t = (tx >= off) ? sd[tx - off] : 0;
        __syncthreads();
        sd[tx] += t;
        __syncthreads();
    }
    if (i < NN) g_start[i] = sd[tx] - v;          // exclusive
    if (tx == SCAN_BLK - 1) g_bsum[blockIdx.x] = sd[tx];
}

// 4b. scan the block partials (tiny) + zero hsum
__global__ void k_scan2() {
    int tx = threadIdx.x;
    if (tx < FOUT) g_hsum[tx] = 0.0f;
    if (tx == 0) {
        int acc = 0;
        for (int b = 0; b < NBLK; b++) {
            int t = g_bsum[b];
            g_bsum[b] = acc;
            acc += t;
        }
    }
}

// 4c. add block offsets, init cursors
__global__ void k_scan3() {
    int i = blockIdx.x * SCAN_BLK + threadIdx.x;
    if (i < NN) {
        int s = g_start[i] + g_bsum[blockIdx.x];
        g_start[i]  = s;
        g_cursor[i] = s;
    }
}

// 5. counting-sort scatter: place row index into its col's bucket
__global__ void k_sort(const int* __restrict__ row, const int* __restrict__ col, int e) {
    int i = blockIdx.x * blockDim.x + threadIdx.x;
    if (i < e) {
        int p = atomicAdd(&g_cursor[col[i]], 1);
        g_srow[p] = row[i];
    }
}

// ---------------------------------------------------------------------------
// 6. SGEMM: y = (A @ W) * dinv[row]. 128x128 tile, K-step 8, 8x8 micro-tile.
__global__ void __launch_bounds__(256, 2)
k_gemm(const float* __restrict__ A, const float* __restrict__ W, int N) {
    __shared__ float As[8][132];
    __shared__ float Bs[8][128];

    const int tx = threadIdx.x;
    const int block_row = blockIdx.x * 128;
    const int tid_r = tx >> 4;
    const int tid_c = tx & 15;

    float acc[8][8];
#pragma unroll
    for (int i = 0; i < 8; i++)
#pragma unroll
        for (int j = 0; j < 8; j++) acc[i][j] = 0.0f;

    const int lrow = tx >> 1;
    const int half = tx & 1;
    const int gr_load = block_row + lrow;
    const int bk = tx >> 5;
    const int bc = tx & 31;

    for (int k0 = 0; k0 < FIN; k0 += 8) {
        float4 av = make_float4(0.f, 0.f, 0.f, 0.f);
        if (gr_load < N)
            av = *(const float4*)(A + (size_t)gr_load * FIN + k0 + half * 4);
        As[half * 4 + 0][lrow] = av.x;
        As[half * 4 + 1][lrow] = av.y;
        As[half * 4 + 2][lrow] = av.z;
        As[half * 4 + 3][lrow] = av.w;

        float4 bv = *(const float4*)(W + (size_t)(k0 + bk) * FOUT + bc * 4);
        *(float4*)&Bs[bk][bc * 4] = bv;

        __syncthreads();
#pragma unroll
        for (int kk = 0; kk < 8; kk++) {
            float a[8], b[8];
#pragma unroll
            for (int i = 0; i < 8; i++) a[i] = As[kk][tid_r * 8 + i];
#pragma unroll
            for (int j = 0; j < 8; j++) b[j] = Bs[kk][tid_c * 8 + j];
#pragma unroll
            for (int i = 0; i < 8; i++)
#pragma unroll
                for (int j = 0; j < 8; j++) acc[i][j] = fmaf(a[i], b[j], acc[i][j]);
        }
        __syncthreads();
    }

#pragma unroll
    for (int i = 0; i < 8; i++) {
        int gr = block_row + tid_r * 8 + i;
        if (gr >= N) continue;
        float dv = g_dinv[gr];
#pragma unroll
        for (int j = 0; j < 8; j += 4) {
            float4 v;
            v.x = acc[i][j + 0] * dv;
            v.y = acc[i][j + 1] * dv;
            v.z = acc[i][j + 2] * dv;
            v.w = acc[i][j + 3] * dv;
            *(float4*)(g_y + (size_t)gr * FOUT + tid_c * 8 + j) = v;
        }
    }
}

// ---------------------------------------------------------------------------
// 7. Gather-aggregate + fused epilogue. One warp per destination node.
//    acc = y[node] (self) + sum over sorted in-edges of y[row].
//    out = relu(dinv[node]*acc + b); accumulate column sums for h.
__global__ void __launch_bounds__(256)
k_agg(const float* __restrict__ b, float* __restrict__ out, int N, int E) {
    __shared__ float hpart[FOUT];
    const int tx = threadIdx.x;
    if (tx < FOUT) hpart[tx] = 0.0f;
    __syncthreads();

    const int lane = tx & 31;
    const int warp = tx >> 5;
    const int node = blockIdx.x * 8 + warp;

    float4 v = make_float4(0.f, 0.f, 0.f, 0.f);
    if (node < N) {
        // self-loop term
        float4 acc = ((const float4*)(g_y + (size_t)node * FOUT))[lane];
        int s  = g_start[node];
        int e2 = (node + 1 < N) ? g_start[node + 1] : E;

        for (int base = s; base < e2; base += 32) {
            int cnt = min(32, e2 - base);
            int myidx = (lane < cnt) ? g_srow[base + lane] : 0;
            int j = 0;
            for (; j + 4 <= cnt; j += 4) {
                int r0 = __shfl_sync(0xffffffffu, myidx, j + 0);
                int r1 = __shfl_sync(0xffffffffu, myidx, j + 1);
                int r2 = __shfl_sync(0xffffffffu, myidx, j + 2);
                int r3 = __shfl_sync(0xffffffffu, myidx, j + 3);
                float4 v0 = ((const float4*)(g_y + (size_t)r0 * FOUT))[lane];
                float4 v1 = ((const float4*)(g_y + (size_t)r1 * FOUT))[lane];
                float4 v2 = ((const float4*)(g_y + (size_t)r2 * FOUT))[lane];
                float4 v3 = ((const float4*)(g_y + (size_t)r3 * FOUT))[lane];
                acc.x += v0.x + v1.x + v2.x + v3.x;
                acc.y += v0.y + v1.y + v2.y + v3.y;
                acc.z += v0.z + v1.z + v2.z + v3.z;
                acc.w += v0.w + v1.w + v2.w + v3.w;
            }
            for (; j < cnt; j++) {
                int r = __shfl_sync(0xffffffffu, myidx, j);
                float4 vv = ((const float4*)(g_y + (size_t)r * FOUT))[lane];
                acc.x += vv.x; acc.y += vv.y; acc.z += vv.z; acc.w += vv.w;
            }
        }

        float dv = g_dinv[node];
        float4 bv = ((const float4*)b)[lane];
        v.x = fmaxf(fmaf(acc.x, dv, bv.x), 0.0f);
        v.y = fmaxf(fmaf(acc.y, dv, bv.y), 0.0f);
        v.z = fmaxf(fmaf(acc.z, dv, bv.z), 0.0f);
        v.w = fmaxf(fmaf(acc.w, dv, bv.w), 0.0f);
        ((float4*)(out + (size_t)node * FOUT))[lane] = v;
    }

    atomicAdd(&hpart[lane * 4 + 0], v.x);
    atomicAdd(&hpart[lane * 4 + 1], v.y);
    atomicAdd(&hpart[lane * 4 + 2], v.z);
    atomicAdd(&hpart[lane * 4 + 3], v.w);
    __syncthreads();
    if (tx < FOUT) atomicAdd(&g_hsum[tx], hpart[tx]);
}

// 8. h = sigmoid(mean)
__global__ void k_h(float* __restrict__ hout, float ninv) {
    int j = threadIdx.x;
    float m = g_hsum[j] * ninv;
    hout[j] = 1.0f / (1.0f + expf(-m));
}

// ---------------------------------------------------------------------------
extern "C" void kernel_launch(void* const* d_in, const int* in_sizes, int n_in,
                              void* d_out, int out_size) {
    const float* feat = (const float*)d_in[0];
    const int*   ei   = (const int*)d_in[1];
    const float* W    = (const float*)d_in[2];
    const float* b    = (const float*)d_in[3];
    float* out = (float*)d_out;

    int N = in_sizes[0] / FIN;
    int E = in_sizes[1] / 2;
    const int* rowp = ei;
    const int* colp = ei + E;

    k_zero<<<(N + 255) / 256, 256>>>(N);
    k_deg<<<(E + 255) / 256, 256>>>(colp, E);
    k_dinv<<<(N + 255) / 256, 256>>>(N);
    k_scan1<<<NBLK, SCAN_BLK>>>();
    k_scan2<<<1, 128>>>();
    k_scan3<<<NBLK, SCAN_BLK>>>();
    k_sort<<<(E + 255) / 256, 256>>>(rowp, colp, E);
    k_gemm<<<(N + 127) / 128, 256>>>(feat, W, N);
    k_agg<<<(N + 7) / 8, 256>>>(b, out, N, E);
    k_h<<<1, FOUT>>>(out + (size_t)N * FOUT, 1.0f / (float)N);
}